// round 1
// baseline (speedup 1.0000x reference)
#include <cuda_runtime.h>
#include <math.h>

#define SEQ 1024
#define DM  1024
#define NH  16
#define HD  64
#define NB  2

// Scratch (device globals: no allocations allowed)
__device__ float g_qproj[NB*SEQ*DM];
__device__ float g_vproj[NB*SEQ*DM];
__device__ float g_x[NB*SEQ*DM];
__device__ float g_posT[HD*2*SEQ + 16];   // [64][2048] transposed pos, +pad for band overread
__device__ float g_vbrel[NH*2*SEQ + 16];  // [16][2048] v_bias . pos, +pad

// ---------------------------------------------------------------------------
// Positional embeddings, stored transposed: g_posT[d][l] = pos[l][d]
// Match reference fp32 rounding of the angle, then accurate sin/cos.
// ---------------------------------------------------------------------------
__global__ void pos_kernel() {
    int l = blockIdx.x * blockDim.x + threadIdx.x;
    if (l >= 2*SEQ) return;
    float p = (float)(l - SEQ);
    const double negc = -log(10000.0) / 31.0;   // half-1 = 31
    for (int j = 0; j < 32; j++) {
        float div = (float)exp((double)j * negc);
        float ang = p * div;                    // fp32 angle (matches jnp fp32)
        double a = (double)ang;
        g_posT[j*2048 + l]        = (float)sin(a);
        g_posT[(j+32)*2048 + l]   = (float)cos(a);
    }
}

// vbrel[h][l] = sum_d v_bias[h][d] * pos[l][d]
__global__ void vbrel_kernel(const float* __restrict__ vb) {
    int l = blockIdx.x * blockDim.x + threadIdx.x;
    if (l >= 2*SEQ) return;
    for (int h = 0; h < NH; h++) {
        float s = 0.f;
        #pragma unroll 8
        for (int d = 0; d < HD; d++)
            s = fmaf(vb[h*HD + d], g_posT[d*2048 + l], s);
        g_vbrel[h*2048 + l] = s;
    }
}

// ---------------------------------------------------------------------------
// SGEMM (NT): C[m][n] = sum_k A[m][k]*B[n][k] + bias[n]
// BM=BN=128, BK=16, 256 threads, 8x8 per thread.
// ---------------------------------------------------------------------------
__global__ __launch_bounds__(256) void sgemm_nt_bias(
    const float* __restrict__ A, const float* __restrict__ B,
    const float* __restrict__ bias, float* __restrict__ C,
    int M, int N, int K)
{
    __shared__ float As[16*132];
    __shared__ float Bs[16*132];
    int tid = threadIdx.x;
    int tx = tid & 15, ty = tid >> 4;
    int row0 = blockIdx.y * 128;
    int col0 = blockIdx.x * 128;

    float acc[8][8];
    #pragma unroll
    for (int i = 0; i < 8; i++)
        #pragma unroll
        for (int j = 0; j < 8; j++) acc[i][j] = 0.f;

    for (int kt = 0; kt < K; kt += 16) {
        #pragma unroll
        for (int r = 0; r < 2; r++) {
            int idx = tid + r*256;
            int m = idx >> 2, kq = idx & 3;
            float4 va = *(const float4*)(A + (size_t)(row0+m)*K + kt + 4*kq);
            As[(4*kq+0)*132 + m] = va.x;
            As[(4*kq+1)*132 + m] = va.y;
            As[(4*kq+2)*132 + m] = va.z;
            As[(4*kq+3)*132 + m] = va.w;
            float4 vb4 = *(const float4*)(B + (size_t)(col0+m)*K + kt + 4*kq);
            Bs[(4*kq+0)*132 + m] = vb4.x;
            Bs[(4*kq+1)*132 + m] = vb4.y;
            Bs[(4*kq+2)*132 + m] = vb4.z;
            Bs[(4*kq+3)*132 + m] = vb4.w;
        }
        __syncthreads();
        #pragma unroll
        for (int k = 0; k < 16; k++) {
            float a[8], b[8];
            *(float4*)&a[0] = *(const float4*)&As[k*132 + ty*8];
            *(float4*)&a[4] = *(const float4*)&As[k*132 + ty*8 + 4];
            *(float4*)&b[0] = *(const float4*)&Bs[k*132 + tx*8];
            *(float4*)&b[4] = *(const float4*)&Bs[k*132 + tx*8 + 4];
            #pragma unroll
            for (int i = 0; i < 8; i++)
                #pragma unroll
                for (int j = 0; j < 8; j++)
                    acc[i][j] = fmaf(a[i], b[j], acc[i][j]);
        }
        __syncthreads();
    }

    float bb[8];
    #pragma unroll
    for (int j = 0; j < 8; j++) bb[j] = bias[col0 + tx*8 + j];
    #pragma unroll
    for (int i = 0; i < 8; i++) {
        float4 o0 = make_float4(acc[i][0]+bb[0], acc[i][1]+bb[1], acc[i][2]+bb[2], acc[i][3]+bb[3]);
        float4 o1 = make_float4(acc[i][4]+bb[4], acc[i][5]+bb[5], acc[i][6]+bb[6], acc[i][7]+bb[7]);
        float* cp = C + (size_t)(row0+ty*8+i)*N + col0 + tx*8;
        *(float4*)cp = o0;
        *(float4*)(cp+4) = o1;
    }
}

// ---------------------------------------------------------------------------
// Fused attention: per CTA a 128-query tile of one (b,h).
// score[q,k] = sum_d q_d*(k_d + posT[d][S+k-q]) + vbrel[h][S+k-q]
// Online softmax (flash), P staged through smem for P@V.
// smem layout (floats):
//   Qs  [128][68]   @ 0        (8704)
//   KV  union: Kst[64][132] / Vs[128][68]  @ 8704  (8704)
//   Ps  [64][256]   @ 17408    (16384)  pos band, Ps[d][m]=posT[d][lmin+m]
//   Pt  [128][132]  @ 33792    (16896)  exp(scores)
//   vbs [256]       @ 50688
// total 50944 floats = 203776 B
// ---------------------------------------------------------------------------
#define ATT_SMEM_FLOATS 50944
#define ATT_SMEM_BYTES  (ATT_SMEM_FLOATS * 4)

__global__ __launch_bounds__(256, 1) void attn_kernel(const float* __restrict__ key)
{
    extern __shared__ float sm[];
    float* Qs  = sm;
    float* KV  = sm + 8704;
    float* Ps  = sm + 17408;
    float* Pt  = sm + 33792;
    float* vbs = sm + 50688;

    int tid = threadIdx.x;
    int tx = tid & 15, ty = tid >> 4;
    int q0 = blockIdx.x * 128;
    int h  = blockIdx.y;
    int b  = blockIdx.z;

    // Load Q tile [128][64] directly (row-major, padded rows of 68)
    const float* qbase = g_qproj + ((size_t)(b*SEQ + q0))*DM + h*HD;
    #pragma unroll
    for (int r = 0; r < 8; r++) {
        int it = tid + r*256;
        int u = it >> 4, dq = it & 15;
        float4 v = *(const float4*)(qbase + (size_t)u*DM + 4*dq);
        *(float4*)&Qs[u*68 + 4*dq] = v;
    }

    float O[8][4];
    float m_run[8], l_run[8];
    #pragma unroll
    for (int i = 0; i < 8; i++) {
        m_run[i] = -INFINITY; l_run[i] = 0.f;
        #pragma unroll
        for (int c = 0; c < 4; c++) O[i][c] = 0.f;
    }

    int u0 = ty*8, w0 = tx*8;
    int mbase = 127 + w0 - u0;   // pos-band index for (i=0,j=0); m(i,j)=mbase+j-i

    const float* kbase = key     + ((size_t)(b*SEQ))*DM + h*HD;
    const float* vbase = g_vproj + ((size_t)(b*SEQ))*DM + h*HD;

    for (int kt = 0; kt < 8; kt++) {
        int k0 = kt*128;
        int lmin = SEQ + k0 - q0 - 127;   // >= 1 always
        __syncthreads();

        // K tile transposed: KV[d][w], rows padded to 132
        #pragma unroll
        for (int r = 0; r < 8; r++) {
            int it = tid + r*256;
            int w = it >> 4, dq = it & 15;
            float4 v = *(const float4*)(kbase + (size_t)(k0+w)*DM + 4*dq);
            KV[(4*dq+0)*132 + w] = v.x;
            KV[(4*dq+1)*132 + w] = v.y;
            KV[(4*dq+2)*132 + w] = v.z;
            KV[(4*dq+3)*132 + w] = v.w;
        }
        // pos band (scalar loads: lmin is odd-aligned)
        for (int it = tid; it < 64*256; it += 256) {
            int d = it >> 8, m = it & 255;
            Ps[it] = g_posT[d*2048 + lmin + m];
        }
        vbs[tid] = g_vbrel[h*2048 + lmin + tid];
        __syncthreads();

        // --- phase 1: scores (qk + rel) ---
        float acc[8][8];
        #pragma unroll
        for (int i = 0; i < 8; i++)
            #pragma unroll
            for (int j = 0; j < 8; j++) acc[i][j] = 0.f;

        #pragma unroll 4
        for (int d = 0; d < 64; d++) {
            float qv[8], kv[8], pv[16];
            #pragma unroll
            for (int i = 0; i < 8; i++) qv[i] = Qs[(u0+i)*68 + d];
            *(float4*)&kv[0] = *(const float4*)&KV[d*132 + w0];
            *(float4*)&kv[4] = *(const float4*)&KV[d*132 + w0 + 4];
            const float* pr = &Ps[d*256 + mbase - 7];
            *(float4*)&pv[0]  = *(const float4*)&pr[0];
            *(float4*)&pv[4]  = *(const float4*)&pr[4];
            *(float4*)&pv[8]  = *(const float4*)&pr[8];
            *(float4*)&pv[12] = *(const float4*)&pr[12];
            #pragma unroll
            for (int i = 0; i < 8; i++)
                #pragma unroll
                for (int j = 0; j < 8; j++)
                    acc[i][j] = fmaf(qv[i], kv[j] + pv[7 + j - i], acc[i][j]);
        }

        // add vbias_rel, row max
        float mt[8];
        #pragma unroll
        for (int i = 0; i < 8; i++) {
            float mm = -INFINITY;
            #pragma unroll
            for (int j = 0; j < 8; j++) {
                acc[i][j] += vbs[mbase + j - i];
                mm = fmaxf(mm, acc[i][j]);
            }
            mt[i] = mm;
        }
        #pragma unroll
        for (int o = 1; o < 16; o <<= 1)
            #pragma unroll
            for (int i = 0; i < 8; i++)
                mt[i] = fmaxf(mt[i], __shfl_xor_sync(0xffffffffu, mt[i], o));

        // online softmax: exp, write P to smem, partial row sums
        float scl[8], ls[8];
        #pragma unroll
        for (int i = 0; i < 8; i++) {
            float mn = fmaxf(m_run[i], mt[i]);
            scl[i] = __expf(m_run[i] - mn);
            m_run[i] = mn;
            float p0 = __expf(acc[i][0]-mn), p1 = __expf(acc[i][1]-mn);
            float p2 = __expf(acc[i][2]-mn), p3 = __expf(acc[i][3]-mn);
            float p4 = __expf(acc[i][4]-mn), p5 = __expf(acc[i][5]-mn);
            float p6 = __expf(acc[i][6]-mn), p7 = __expf(acc[i][7]-mn);
            *(float4*)&Pt[(u0+i)*132 + w0]     = make_float4(p0,p1,p2,p3);
            *(float4*)&Pt[(u0+i)*132 + w0 + 4] = make_float4(p4,p5,p6,p7);
            ls[i] = ((p0+p1)+(p2+p3)) + ((p4+p5)+(p6+p7));
        }
        #pragma unroll
        for (int o = 1; o < 16; o <<= 1)
            #pragma unroll
            for (int i = 0; i < 8; i++)
                ls[i] += __shfl_xor_sync(0xffffffffu, ls[i], o);
        #pragma unroll
        for (int i = 0; i < 8; i++)
            l_run[i] = l_run[i]*scl[i] + ls[i];

        __syncthreads();
        // load V tile into the K buffer: Vs[w][d], rows padded to 68
        #pragma unroll
        for (int r = 0; r < 8; r++) {
            int it = tid + r*256;
            int w = it >> 4, dq = it & 15;
            float4 v = *(const float4*)(vbase + (size_t)(k0+w)*DM + 4*dq);
            *(float4*)&KV[w*68 + 4*dq] = v;
        }
        __syncthreads();

        // --- phase 2: O = O*scl + P @ V ---
        #pragma unroll
        for (int i = 0; i < 8; i++) {
            O[i][0] *= scl[i]; O[i][1] *= scl[i];
            O[i][2] *= scl[i]; O[i][3] *= scl[i];
        }
        #pragma unroll 4
        for (int w = 0; w < 128; w++) {
            float4 vv = *(const float4*)&KV[w*68 + 4*tx];
            #pragma unroll
            for (int i = 0; i < 8; i++) {
                float p = Pt[(u0+i)*132 + w];
                O[i][0] = fmaf(p, vv.x, O[i][0]);
                O[i][1] = fmaf(p, vv.y, O[i][1]);
                O[i][2] = fmaf(p, vv.z, O[i][2]);
                O[i][3] = fmaf(p, vv.w, O[i][3]);
            }
        }
    }

    // epilogue: normalize, write x as [B,S,H*dv]
    float* xbase = g_x + ((size_t)(b*SEQ + q0))*DM + h*HD;
    #pragma unroll
    for (int i = 0; i < 8; i++) {
        float inv = 1.f / l_run[i];
        float4 o = make_float4(O[i][0]*inv, O[i][1]*inv, O[i][2]*inv, O[i][3]*inv);
        *(float4*)(xbase + (size_t)(u0+i)*DM + 4*tx) = o;
    }
}

// ---------------------------------------------------------------------------
extern "C" void kernel_launch(void* const* d_in, const int* in_sizes, int n_in,
                              void* d_out, int out_size) {
    const float* query  = (const float*)d_in[0];
    const float* key    = (const float*)d_in[1];
    const float* value  = (const float*)d_in[2];
    /* d_in[3] = mask: unused by reference */
    const float* Wq     = (const float*)d_in[4];
    const float* bq     = (const float*)d_in[5];
    const float* Wv     = (const float*)d_in[6];
    const float* bv     = (const float*)d_in[7];
    const float* Wo     = (const float*)d_in[8];
    const float* bo     = (const float*)d_in[9];
    const float* v_bias = (const float*)d_in[10];
    float* out = (float*)d_out;

    void *qp, *vp, *xp;
    cudaGetSymbolAddress(&qp, g_qproj);
    cudaGetSymbolAddress(&vp, g_vproj);
    cudaGetSymbolAddress(&xp, g_x);

    cudaFuncSetAttribute(attn_kernel,
                         cudaFuncAttributeMaxDynamicSharedMemorySize,
                         ATT_SMEM_BYTES);

    pos_kernel<<<8, 256>>>();
    vbrel_kernel<<<8, 256>>>(v_bias);

    dim3 ggrid(DM/128, (NB*SEQ)/128);  // (8, 16)
    sgemm_nt_bias<<<ggrid, 256>>>(query, Wq, bq, (float*)qp, NB*SEQ, DM, DM);
    sgemm_nt_bias<<<ggrid, 256>>>(value, Wv, bv, (float*)vp, NB*SEQ, DM, DM);

    dim3 agrid(SEQ/128, NH, NB);       // (8, 16, 2)
    attn_kernel<<<agrid, 256, ATT_SMEM_BYTES>>>(key);

    sgemm_nt_bias<<<ggrid, 256>>>((const float*)xp, Wo, bo, out, NB*SEQ, DM, DM);
}

// round 4
// speedup vs baseline: 1.2903x; 1.2903x over previous
#include <cuda_runtime.h>
#include <cuda_bf16.h>
#include <math.h>
#include <stdint.h>

#define SEQ 1024
#define DM  1024
#define NH  16
#define HD  64
#define NB  2
#define GK  1024

// Scratch (device globals: no allocations allowed)
__device__ float g_qproj[NB*SEQ*DM];
__device__ float g_vproj[NB*SEQ*DM];
__device__ float g_x[NB*SEQ*DM];
__device__ float g_posT[HD*2*SEQ + 16];   // [64][2048] transposed pos, +pad
__device__ float g_vbrel[NH*2*SEQ + 16];  // [16][2048] v_bias . pos, +pad

// ---------------------------------------------------------------------------
// helpers (generic sm_80+ PTX only: ldmatrix + mma.sync — NO tcgen05!)
// ---------------------------------------------------------------------------
__device__ __forceinline__ uint32_t smem_u32(const void* p) {
    uint32_t a;
    asm("{ .reg .u64 t; cvta.to.shared.u64 t, %1; cvt.u32.u64 %0, t; }" : "=r"(a) : "l"(p));
    return a;
}

__device__ __forceinline__ void ldsm_x4(uint32_t (&r)[4], uint32_t addr) {
    asm volatile("ldmatrix.sync.aligned.m8n8.x4.shared.b16 {%0,%1,%2,%3}, [%4];"
        : "=r"(r[0]), "=r"(r[1]), "=r"(r[2]), "=r"(r[3]) : "r"(addr));
}

__device__ __forceinline__ void mma_bf16(float (&d)[4], const uint32_t (&a)[4],
                                         uint32_t b0, uint32_t b1) {
    asm volatile("mma.sync.aligned.m16n8k16.row.col.f32.bf16.bf16.f32 "
        "{%0,%1,%2,%3}, {%4,%5,%6,%7}, {%8,%9}, {%0,%1,%2,%3};"
        : "+f"(d[0]), "+f"(d[1]), "+f"(d[2]), "+f"(d[3])
        : "r"(a[0]), "r"(a[1]), "r"(a[2]), "r"(a[3]), "r"(b0), "r"(b1));
}

// split fp32 float4 -> bf16 hi + bf16 lo, store 8B each to smem
__device__ __forceinline__ void split_sts(float4 v, char* hi, char* lo, int byteoff) {
    __nv_bfloat162 h01 = __floats2bfloat162_rn(v.x, v.y);
    __nv_bfloat162 h23 = __floats2bfloat162_rn(v.z, v.w);
    float2 f01 = __bfloat1622float2(h01);
    float2 f23 = __bfloat1622float2(h23);
    __nv_bfloat162 l01 = __floats2bfloat162_rn(v.x - f01.x, v.y - f01.y);
    __nv_bfloat162 l23 = __floats2bfloat162_rn(v.z - f23.x, v.w - f23.y);
    *(uint2*)(hi + byteoff) = make_uint2(*(uint32_t*)&h01, *(uint32_t*)&h23);
    *(uint2*)(lo + byteoff) = make_uint2(*(uint32_t*)&l01, *(uint32_t*)&l23);
}

// ---------------------------------------------------------------------------
// Positional embeddings, stored transposed: g_posT[d][l] = pos[l][d]
// ---------------------------------------------------------------------------
__global__ void pos_kernel() {
    int l = blockIdx.x * blockDim.x + threadIdx.x;
    if (l >= 2*SEQ) return;
    float p = (float)(l - SEQ);
    const double negc = -log(10000.0) / 31.0;   // half-1 = 31
    for (int j = 0; j < 32; j++) {
        float div = (float)exp((double)j * negc);
        float ang = p * div;                    // fp32 angle (matches jnp fp32)
        double a = (double)ang;
        g_posT[j*2048 + l]        = (float)sin(a);
        g_posT[(j+32)*2048 + l]   = (float)cos(a);
    }
}

// vbrel[h][l] = sum_d v_bias[h][d] * pos[l][d]
__global__ void vbrel_kernel(const float* __restrict__ vb) {
    int l = blockIdx.x * blockDim.x + threadIdx.x;
    if (l >= 2*SEQ) return;
    for (int h = 0; h < NH; h++) {
        float s = 0.f;
        #pragma unroll 8
        for (int d = 0; d < HD; d++)
            s = fmaf(vb[h*HD + d], g_posT[d*2048 + l], s);
        g_vbrel[h*2048 + l] = s;
    }
}

// ---------------------------------------------------------------------------
// bf16x2-split tensor-core GEMM (NT): C[m][n] = sum_k A[m][k]*B[n][k] + bias[n]
// 128x128 CTA tile, 8 warps (2x4) of 64x32, K-step 32, double-buffered smem.
// smem tiles: [128 rows][stride 40 bf16] = 10240 B each (80B rows: 8 distinct
// banks per ldmatrix phase). Per buf: Ahi Alo Bhi Blo = 40960 B; x2 = 80 KB
// dynamic smem.
// ---------------------------------------------------------------------------
#define TSTRIDE 40
#define TILE_B  (128 * TSTRIDE * 2)      // 10240
#define BUF_B   (4 * TILE_B)             // 40960
#define HG_SMEM (2 * BUF_B)              // 81920

__global__ __launch_bounds__(256) void hgemm_nt_bias(
    const float* __restrict__ A, const float* __restrict__ B,
    const float* __restrict__ bias, float* __restrict__ C,
    int M, int N)
{
    extern __shared__ __align__(16) char smraw[];
    const int tid = threadIdx.x, lane = tid & 31, wid = tid >> 5;
    const int wm = wid & 1, wn = wid >> 1;
    const int row0 = blockIdx.y * 128, col0 = blockIdx.x * 128;

    // loader: thread handles row lr, 16 floats starting at col lc of each k32 chunk
    const int lr = tid >> 1, lc = (tid & 1) * 16;
    const float* Ap = A + (size_t)(row0 + lr) * GK + lc;
    const float* Bp = B + (size_t)(col0 + lr) * GK + lc;

    const uint32_t sbase = smem_u32(smraw);

    // ldmatrix lane addressing (x4, non-trans, canonical 16x16 tiles)
    const int a_r = lane & 15;              // row within 16-row group
    const int a_c = (lane >> 4) << 3;       // k-offset 0 or 8
    const int b_r = (lane & 7) + ((lane & 16) >> 1);  // n within 16
    const int b_c = lane & 8;               // k-offset 0 or 8

    float acc[4][4][4];
    #pragma unroll
    for (int i = 0; i < 4; i++)
        #pragma unroll
        for (int j = 0; j < 4; j++)
            #pragma unroll
            for (int c = 0; c < 4; c++) acc[i][j][c] = 0.f;

    float4 av[4], bv[4];
    // prologue: load + stage k-chunk 0 into buf 0
    #pragma unroll
    for (int q = 0; q < 4; q++) {
        av[q] = *(const float4*)(Ap + 4*q);
        bv[q] = *(const float4*)(Bp + 4*q);
    }
    {
        char* hA = smraw;
        const int bo = (lr*TSTRIDE + lc) * 2;
        #pragma unroll
        for (int q = 0; q < 4; q++) {
            split_sts(av[q], hA,            hA + TILE_B,   bo + 8*q);
            split_sts(bv[q], hA + 2*TILE_B, hA + 3*TILE_B, bo + 8*q);
        }
    }
    __syncthreads();

    for (int kt = 0; kt < 32; kt++) {
        // prefetch next chunk from global
        if (kt < 31) {
            #pragma unroll
            for (int q = 0; q < 4; q++) {
                av[q] = *(const float4*)(Ap + (kt+1)*32 + 4*q);
                bv[q] = *(const float4*)(Bp + (kt+1)*32 + 4*q);
            }
        }

        // compute on buffer kt&1
        const uint32_t base = sbase + (kt & 1) * BUF_B;
        const uint32_t aHi = base,              aLo = base + TILE_B;
        const uint32_t bHi = base + 2*TILE_B,   bLo = base + 3*TILE_B;

        #pragma unroll
        for (int kk = 0; kk < 2; kk++) {
            const int koff = kk * 16;
            uint32_t ah[4][4], al[4][4];
            #pragma unroll
            for (int i = 0; i < 4; i++) {
                const uint32_t off = (uint32_t)(((wm*64 + i*16 + a_r)*TSTRIDE + koff + a_c) * 2);
                ldsm_x4(ah[i], aHi + off);
                ldsm_x4(al[i], aLo + off);
            }
            uint32_t bh[2][4], bl[2][4];
            #pragma unroll
            for (int p = 0; p < 2; p++) {
                const uint32_t off = (uint32_t)(((wn*32 + p*16 + b_r)*TSTRIDE + koff + b_c) * 2);
                ldsm_x4(bh[p], bHi + off);
                ldsm_x4(bl[p], bLo + off);
            }
            #pragma unroll
            for (int i = 0; i < 4; i++)
                #pragma unroll
                for (int j = 0; j < 4; j++) {
                    const int p = j >> 1, s = (j & 1) * 2;
                    mma_bf16(acc[i][j], ah[i], bh[p][s], bh[p][s+1]);  // hi*hi
                    mma_bf16(acc[i][j], ah[i], bl[p][s], bl[p][s+1]);  // hi*lo
                    mma_bf16(acc[i][j], al[i], bh[p][s], bh[p][s+1]);  // lo*hi
                }
        }

        // stage next chunk into buffer (kt+1)&1
        if (kt < 31) {
            char* hA = smraw + ((kt+1) & 1) * BUF_B;
            const int bo = (lr*TSTRIDE + lc) * 2;
            #pragma unroll
            for (int q = 0; q < 4; q++) {
                split_sts(av[q], hA,            hA + TILE_B,   bo + 8*q);
                split_sts(bv[q], hA + 2*TILE_B, hA + 3*TILE_B, bo + 8*q);
            }
            __syncthreads();
        }
    }

    // epilogue: mma C layout -> global, add bias
    const int grp = lane >> 2, qid = lane & 3;
    #pragma unroll
    for (int j = 0; j < 4; j++) {
        const int col = col0 + wn*32 + j*8 + qid*2;
        const float2 bj = *(const float2*)(bias + col);
        #pragma unroll
        for (int i = 0; i < 4; i++) {
            const int row = row0 + wm*64 + i*16 + grp;
            float2 o0 = make_float2(acc[i][j][0] + bj.x, acc[i][j][1] + bj.y);
            float2 o1 = make_float2(acc[i][j][2] + bj.x, acc[i][j][3] + bj.y);
            *(float2*)(C + (size_t)row * N + col)       = o0;
            *(float2*)(C + (size_t)(row + 8) * N + col) = o1;
        }
    }
}

// ---------------------------------------------------------------------------
// Fused attention (fp32, proven round-1 version): per CTA a 128-query tile.
// ---------------------------------------------------------------------------
#define ATT_SMEM_FLOATS 50944
#define ATT_SMEM_BYTES  (ATT_SMEM_FLOATS * 4)

__global__ __launch_bounds__(256, 1) void attn_kernel(const float* __restrict__ key)
{
    extern __shared__ float smf[];
    float* Qs  = smf;
    float* KV  = smf + 8704;
    float* Ps  = smf + 17408;
    float* Pt  = smf + 33792;
    float* vbs = smf + 50688;

    int tid = threadIdx.x;
    int tx = tid & 15, ty = tid >> 4;
    int q0 = blockIdx.x * 128;
    int h  = blockIdx.y;
    int b  = blockIdx.z;

    const float* qbase = g_qproj + ((size_t)(b*SEQ + q0))*DM + h*HD;
    #pragma unroll
    for (int r = 0; r < 8; r++) {
        int it = tid + r*256;
        int u = it >> 4, dq = it & 15;
        float4 v = *(const float4*)(qbase + (size_t)u*DM + 4*dq);
        *(float4*)&Qs[u*68 + 4*dq] = v;
    }

    float O[8][4];
    float m_run[8], l_run[8];
    #pragma unroll
    for (int i = 0; i < 8; i++) {
        m_run[i] = -INFINITY; l_run[i] = 0.f;
        #pragma unroll
        for (int c = 0; c < 4; c++) O[i][c] = 0.f;
    }

    int u0 = ty*8, w0 = tx*8;
    int mbase = 127 + w0 - u0;

    const float* kbase = key     + ((size_t)(b*SEQ))*DM + h*HD;
    const float* vbase = g_vproj + ((size_t)(b*SEQ))*DM + h*HD;

    for (int kt = 0; kt < 8; kt++) {
        int k0 = kt*128;
        int lmin = SEQ + k0 - q0 - 127;
        __syncthreads();

        #pragma unroll
        for (int r = 0; r < 8; r++) {
            int it = tid + r*256;
            int w = it >> 4, dq = it & 15;
            float4 v = *(const float4*)(kbase + (size_t)(k0+w)*DM + 4*dq);
            KV[(4*dq+0)*132 + w] = v.x;
            KV[(4*dq+1)*132 + w] = v.y;
            KV[(4*dq+2)*132 + w] = v.z;
            KV[(4*dq+3)*132 + w] = v.w;
        }
        for (int it = tid; it < 64*256; it += 256) {
            int d = it >> 8, m = it & 255;
            Ps[it] = g_posT[d*2048 + lmin + m];
        }
        vbs[tid] = g_vbrel[h*2048 + lmin + tid];
        __syncthreads();

        float acc[8][8];
        #pragma unroll
        for (int i = 0; i < 8; i++)
            #pragma unroll
            for (int j = 0; j < 8; j++) acc[i][j] = 0.f;

        #pragma unroll 4
        for (int d = 0; d < 64; d++) {
            float qv[8], kv[8], pv[16];
            #pragma unroll
            for (int i = 0; i < 8; i++) qv[i] = Qs[(u0+i)*68 + d];
            *(float4*)&kv[0] = *(const float4*)&KV[d*132 + w0];
            *(float4*)&kv[4] = *(const float4*)&KV[d*132 + w0 + 4];
            const float* pr = &Ps[d*256 + mbase - 7];
            *(float4*)&pv[0]  = *(const float4*)&pr[0];
            *(float4*)&pv[4]  = *(const float4*)&pr[4];
            *(float4*)&pv[8]  = *(const float4*)&pr[8];
            *(float4*)&pv[12] = *(const float4*)&pr[12];
            #pragma unroll
            for (int i = 0; i < 8; i++)
                #pragma unroll
                for (int j = 0; j < 8; j++)
                    acc[i][j] = fmaf(qv[i], kv[j] + pv[7 + j - i], acc[i][j]);
        }

        float mt[8];
        #pragma unroll
        for (int i = 0; i < 8; i++) {
            float mm = -INFINITY;
            #pragma unroll
            for (int j = 0; j < 8; j++) {
                acc[i][j] += vbs[mbase + j - i];
                mm = fmaxf(mm, acc[i][j]);
            }
            mt[i] = mm;
        }
        #pragma unroll
        for (int o = 1; o < 16; o <<= 1)
            #pragma unroll
            for (int i = 0; i < 8; i++)
                mt[i] = fmaxf(mt[i], __shfl_xor_sync(0xffffffffu, mt[i], o));

        float scl[8], ls[8];
        #pragma unroll
        for (int i = 0; i < 8; i++) {
            float mn = fmaxf(m_run[i], mt[i]);
            scl[i] = __expf(m_run[i] - mn);
            m_run[i] = mn;
            float p0 = __expf(acc[i][0]-mn), p1 = __expf(acc[i][1]-mn);
            float p2 = __expf(acc[i][2]-mn), p3 = __expf(acc[i][3]-mn);
            float p4 = __expf(acc[i][4]-mn), p5 = __expf(acc[i][5]-mn);
            float p6 = __expf(acc[i][6]-mn), p7 = __expf(acc[i][7]-mn);
            *(float4*)&Pt[(u0+i)*132 + w0]     = make_float4(p0,p1,p2,p3);
            *(float4*)&Pt[(u0+i)*132 + w0 + 4] = make_float4(p4,p5,p6,p7);
            ls[i] = ((p0+p1)+(p2+p3)) + ((p4+p5)+(p6+p7));
        }
        #pragma unroll
        for (int o = 1; o < 16; o <<= 1)
            #pragma unroll
            for (int i = 0; i < 8; i++)
                ls[i] += __shfl_xor_sync(0xffffffffu, ls[i], o);
        #pragma unroll
        for (int i = 0; i < 8; i++)
            l_run[i] = l_run[i]*scl[i] + ls[i];

        __syncthreads();
        #pragma unroll
        for (int r = 0; r < 8; r++) {
            int it = tid + r*256;
            int w = it >> 4, dq = it & 15;
            float4 v = *(const float4*)(vbase + (size_t)(k0+w)*DM + 4*dq);
            *(float4*)&KV[w*68 + 4*dq] = v;
        }
        __syncthreads();

        #pragma unroll
        for (int i = 0; i < 8; i++) {
            O[i][0] *= scl[i]; O[i][1] *= scl[i];
            O[i][2] *= scl[i]; O[i][3] *= scl[i];
        }
        #pragma unroll 4
        for (int w = 0; w < 128; w++) {
            float4 vv = *(const float4*)&KV[w*68 + 4*tx];
            #pragma unroll
            for (int i = 0; i < 8; i++) {
                float p = Pt[(u0+i)*132 + w];
                O[i][0] = fmaf(p, vv.x, O[i][0]);
                O[i][1] = fmaf(p, vv.y, O[i][1]);
                O[i][2] = fmaf(p, vv.z, O[i][2]);
                O[i][3] = fmaf(p, vv.w, O[i][3]);
            }
        }
    }

    float* xbase = g_x + ((size_t)(b*SEQ + q0))*DM + h*HD;
    #pragma unroll
    for (int i = 0; i < 8; i++) {
        float inv = 1.f / l_run[i];
        float4 o = make_float4(O[i][0]*inv, O[i][1]*inv, O[i][2]*inv, O[i][3]*inv);
        *(float4*)(xbase + (size_t)(u0+i)*DM + 4*tx) = o;
    }
}

// ---------------------------------------------------------------------------
extern "C" void kernel_launch(void* const* d_in, const int* in_sizes, int n_in,
                              void* d_out, int out_size) {
    const float* query  = (const float*)d_in[0];
    const float* key    = (const float*)d_in[1];
    const float* value  = (const float*)d_in[2];
    /* d_in[3] = mask: unused by reference */
    const float* Wq     = (const float*)d_in[4];
    const float* bq     = (const float*)d_in[5];
    const float* Wv     = (const float*)d_in[6];
    const float* bv     = (const float*)d_in[7];
    const float* Wo     = (const float*)d_in[8];
    const float* bo     = (const float*)d_in[9];
    const float* v_bias = (const float*)d_in[10];
    float* out = (float*)d_out;

    void *qp, *vp, *xp;
    cudaGetSymbolAddress(&qp, g_qproj);
    cudaGetSymbolAddress(&vp, g_vproj);
    cudaGetSymbolAddress(&xp, g_x);

    cudaFuncSetAttribute(attn_kernel,
                         cudaFuncAttributeMaxDynamicSharedMemorySize,
                         ATT_SMEM_BYTES);
    cudaFuncSetAttribute(hgemm_nt_bias,
                         cudaFuncAttributeMaxDynamicSharedMemorySize,
                         HG_SMEM);

    pos_kernel<<<8, 256>>>();
    vbrel_kernel<<<8, 256>>>(v_bias);

    dim3 ggrid(DM/128, (NB*SEQ)/128);  // (8, 16)
    hgemm_nt_bias<<<ggrid, 256, HG_SMEM>>>(query, Wq, bq, (float*)qp, NB*SEQ, DM);
    hgemm_nt_bias<<<ggrid, 256, HG_SMEM>>>(value, Wv, bv, (float*)vp, NB*SEQ, DM);

    dim3 agrid(SEQ/128, NH, NB);       // (8, 16, 2)
    attn_kernel<<<agrid, 256, ATT_SMEM_BYTES>>>(key);

    hgemm_nt_bias<<<ggrid, 256, HG_SMEM>>>((const float*)xp, Wo, bo, out, NB*SEQ, DM);
}